// round 14
// baseline (speedup 1.0000x reference)
#include <cuda_runtime.h>
#include <cuda_fp16.h>
#include <math.h>
#include <stdint.h>

#define CC 256
#define HWSZ 4096
#define BATCH 4
#define NHEAD 4
#define NBH 16

// -------- scratch (device globals; no allocations allowed) --------
__device__ __half g_ht [(size_t)BATCH * HWSZ * CC];      // normalized input, [b][tok][c] half
__device__ __half g_oh [(size_t)BATCH * HWSZ * CC];      // attention out, [b][tok][c] half
__device__ __half g_qh [(size_t)NBH * HWSZ * 64];        // q: [bh][tok][c] half, *0.125*log2e
__device__ __half g_kh [(size_t)NBH * HWSZ * 64];        // k: [bh][tok][c] half
__device__ __half g_vh [(size_t)NBH * 64 * HWSZ];        // v: [bh][c][tok] half
__device__ __half g_wqkv[768 * 256];                     // fp16 weights
__device__ __half g_wproj[256 * 256];
__device__ float2 g_part[512];                           // per-slice (sum, sumsq)
__device__ float2 g_stats[32];                           // per (b,group) (mean, rstd)

// ============================================================
// helpers (sm_80-baseline PTX only)
// ============================================================
__device__ __forceinline__ uint32_t smem_u32(const void* p) {
    uint32_t a;
    asm("{ .reg .u64 t; cvta.to.shared.u64 t, %1; cvt.u32.u64 %0, t; }" : "=r"(a) : "l"(p));
    return a;
}
__device__ __forceinline__ float ex2f(float x) {
    float r;
    asm("ex2.approx.ftz.f32 %0, %1;" : "=f"(r) : "f"(x));
    return r;
}
__device__ __forceinline__ uint32_t pack_h2(float lo, float hi) {
    uint32_t d;
    asm("cvt.rn.f16x2.f32 %0, %1, %2;" : "=r"(d) : "f"(hi), "f"(lo));
    return d;
}
__device__ __forceinline__ void cp16(uint32_t dst, const void* src) {
    asm volatile("cp.async.cg.shared.global [%0], [%1], 16;" :: "r"(dst), "l"(src) : "memory");
}
#define CP_COMMIT()  asm volatile("cp.async.commit_group;" ::: "memory")
#define CP_WAIT0()   asm volatile("cp.async.wait_group 0;" ::: "memory")
#define CP_WAIT1()   asm volatile("cp.async.wait_group 1;" ::: "memory")

__device__ __forceinline__ void ldsm4(uint32_t r[4], uint32_t addr) {
    asm volatile("ldmatrix.sync.aligned.m8n8.x4.shared.b16 {%0,%1,%2,%3}, [%4];"
        : "=r"(r[0]), "=r"(r[1]), "=r"(r[2]), "=r"(r[3]) : "r"(addr));
}

// fp16 m16n8k16, fp32 accum
__device__ __forceinline__ void mma16(float c[4], const uint32_t a_[4], uint32_t b0, uint32_t b1) {
    asm volatile("mma.sync.aligned.m16n8k16.row.col.f32.f16.f16.f32 "
        "{%0,%1,%2,%3}, {%4,%5,%6,%7}, {%8,%9}, {%0,%1,%2,%3};"
        : "+f"(c[0]), "+f"(c[1]), "+f"(c[2]), "+f"(c[3])
        : "r"(a_[0]), "r"(a_[1]), "r"(a_[2]), "r"(a_[3]),
          "r"(b0), "r"(b1));
}

// ============================================================
// GroupNorm partial stats (blocks 0..511) + weight fp16 convert
// (blocks 512..831), fused to save a launch. 256 threads.
// ============================================================
__global__ void gn_partial_conv_kernel(const float* __restrict__ x,
                                       const float* __restrict__ qkv_w,
                                       const float* __restrict__ proj_w) {
    const int bid = blockIdx.x;
    const int tid = threadIdx.x;
    if (bid < 512) {
        // GN partial: slice of 8192 floats
        const float* xp = x + (size_t)bid * 8192;
        float s = 0.f, ss = 0.f;
        #pragma unroll 8
        for (int i = tid * 4; i < 8192; i += 1024) {
            float4 v = *(const float4*)(xp + i);
            s  += v.x + v.y + v.z + v.w;
            ss += v.x * v.x + v.y * v.y + v.z * v.z + v.w * v.w;
        }
        __shared__ float rs[256], rss[256];
        rs[tid] = s; rss[tid] = ss;
        __syncthreads();
        for (int o = 128; o > 0; o >>= 1) {
            if (tid < o) { rs[tid] += rs[tid + o]; rss[tid] += rss[tid + o]; }
            __syncthreads();
        }
        if (tid == 0) g_part[bid] = make_float2(rs[0], rss[0]);
    } else {
        int i = ((bid - 512) * 256 + tid) * 4;
        float4 v;
        if (i < 768 * 256) {
            v = *(const float4*)(qkv_w + i);
            *(__half2*)(g_wqkv + i)     = __floats2half2_rn(v.x, v.y);
            *(__half2*)(g_wqkv + i + 2) = __floats2half2_rn(v.z, v.w);
        } else {
            int k = i - 768 * 256;
            v = *(const float4*)(proj_w + k);
            *(__half2*)(g_wproj + k)     = __floats2half2_rn(v.x, v.y);
            *(__half2*)(g_wproj + k + 2) = __floats2half2_rn(v.z, v.w);
        }
    }
}

__global__ void gn_final_kernel() {
    int t = threadIdx.x;   // 32 threads; 16 slices each
    float s = 0.f, ss = 0.f;
    #pragma unroll
    for (int i = 0; i < 16; i++) { float2 p = g_part[t * 16 + i]; s += p.x; ss += p.y; }
    float mean = s / 131072.f;
    float var  = ss / 131072.f - mean * mean;
    g_stats[t] = make_float2(mean, rsqrtf(var + 1e-5f));
}

__global__ void gn_norm_kernel(const float* __restrict__ x,
                               const float* __restrict__ w,
                               const float* __restrict__ b) {
    __shared__ float tile[32][129];
    const int t0 = blockIdx.x * 128;
    const int bg = blockIdx.y;
    const int bb = bg >> 3, gg = bg & 7;
    const int tid = threadIdx.x;

    const float* xp = x + ((size_t)bb * 256 + gg * 32) * HWSZ + t0;
    #pragma unroll 4
    for (int i = tid; i < 1024; i += 256) {
        int row = i >> 5, c4 = i & 31;
        float4 v = *(const float4*)(xp + (size_t)row * HWSZ + c4 * 4);
        tile[row][c4 * 4 + 0] = v.x;
        tile[row][c4 * 4 + 1] = v.y;
        tile[row][c4 * 4 + 2] = v.z;
        tile[row][c4 * 4 + 3] = v.w;
    }
    float2 st = g_stats[bg];
    __syncthreads();

    const int tok = tid >> 1, seg = tid & 1;
    __half hv[16];
    #pragma unroll
    for (int i = 0; i < 16; i++) {
        int cc = seg * 16 + i;
        int c = gg * 32 + cc;
        float sc = st.y * w[c];
        float of = b[c] - st.x * sc;
        hv[i] = __float2half_rn(tile[cc][tok] * sc + of);
    }
    __half* dst = g_ht + ((size_t)bb * HWSZ + t0 + tok) * 256 + gg * 32 + seg * 16;
    *(uint4*)dst       = *(uint4*)hv;
    *(uint4*)(dst + 8) = *(uint4*)(hv + 8);
}

// ============================================================
// fp16 tensor-core GEMM (R12 proven config).
// ============================================================
#define LDWH 20
#define TILEW (128 * LDWH)
#define GEMM_SMEM_BYTES (4 * TILEW * 4)
#define QSCALE 0.18033688011112042f
#define EPL 136

template<int M_TOTAL, bool QKV_MODE>
__global__ void __launch_bounds__(256, 2) gemm_h_kernel(
        const __half* __restrict__ A,
        const __half* __restrict__ Bt,
        const float* __restrict__ bias,
        const float* __restrict__ resid,
        float* __restrict__ out) {
    extern __shared__ uint32_t sw[];
    uint32_t* a_s = sw;
    uint32_t* b_s = sw + 2 * TILEW;
    const uint32_t a_u = smem_u32(a_s);
    const uint32_t b_u = smem_u32(b_s);

    const int tid = threadIdx.x, lane = tid & 31, wid = tid >> 5;
    const int g4 = lane >> 2, t4 = lane & 3;
    const int wm = wid >> 1, wn = wid & 1;
    const int bb = blockIdx.z;
    const int m0 = blockIdx.y * 128;
    const int n0 = blockIdx.x * 128;
    const __half* Bp = Bt + (size_t)bb * HWSZ * 256 + (size_t)n0 * 256;

    float acc[2][8][4];
    #pragma unroll
    for (int mt = 0; mt < 2; mt++)
        #pragma unroll
        for (int nt = 0; nt < 8; nt++)
            #pragma unroll
            for (int i = 0; i < 4; i++) acc[mt][nt][i] = 0.f;

    #pragma unroll 2
    for (int e = tid; e < 512; e += 256) {
        int r = e >> 2, c8 = e & 3;
        cp16(a_u + (r * LDWH + c8 * 4) * 4, A + (size_t)(m0 + r) * 256 + c8 * 8);
    }
    #pragma unroll 2
    for (int e = tid; e < 512; e += 256) {
        int r = e >> 2, c8 = e & 3;
        cp16(b_u + (r * LDWH + c8 * 4) * 4, Bp + (size_t)r * 256 + c8 * 8);
    }
    CP_COMMIT();

    for (int j = 0; j < 8; j++) {
        const int buf = j & 1;
        const uint32_t* at = a_s + buf * TILEW;
        const uint32_t* bt = b_s + buf * TILEW;

        CP_WAIT0();
        __syncthreads();

        if (j < 7) {
            const uint32_t ad = a_u + ((buf ^ 1) * TILEW) * 4;
            const uint32_t bd = b_u + ((buf ^ 1) * TILEW) * 4;
            const int k0 = (j + 1) * 32;
            #pragma unroll 2
            for (int e = tid; e < 512; e += 256) {
                int r = e >> 2, c8 = e & 3;
                cp16(ad + (r * LDWH + c8 * 4) * 4, A + (size_t)(m0 + r) * 256 + k0 + c8 * 8);
            }
            #pragma unroll 2
            for (int e = tid; e < 512; e += 256) {
                int r = e >> 2, c8 = e & 3;
                cp16(bd + (r * LDWH + c8 * 4) * 4, Bp + (size_t)r * 256 + k0 + c8 * 8);
            }
            CP_COMMIT();
        }

        #pragma unroll
        for (int kt = 0; kt < 2; kt++) {
            uint32_t af[2][4];
            #pragma unroll
            for (int mt = 0; mt < 2; mt++) {
                const uint32_t* ap = at + (wm * 32 + mt * 16 + g4) * LDWH + kt * 8 + t4;
                af[mt][0] = ap[0];
                af[mt][1] = ap[8 * LDWH];
                af[mt][2] = ap[4];
                af[mt][3] = ap[8 * LDWH + 4];
            }
            const uint32_t* bp = bt + (wn * 64 + g4) * LDWH + kt * 8 + t4;
            #pragma unroll
            for (int nt = 0; nt < 8; nt++) {
                uint32_t b0 = bp[nt * 8 * LDWH];
                uint32_t b1 = bp[nt * 8 * LDWH + 4];
                mma16(acc[0][nt], af[0], b0, b1);
                mma16(acc[1][nt], af[1], b0, b1);
            }
        }
        __syncthreads();
    }

    // ---- epilogue ----
    if (QKV_MODE) {
        uint16_t* ep = (uint16_t*)sw;
        const bool is_v = (m0 >= 512);
        const float sc = (m0 < 256) ? QSCALE : 1.0f;

        #pragma unroll
        for (int mt = 0; mt < 2; mt++) {
            const int r = wm * 32 + mt * 16 + g4;
            const float bv0 = bias[m0 + r], bv1 = bias[m0 + r + 8];
            #pragma unroll
            for (int nt = 0; nt < 8; nt++) {
                const int tl = wn * 64 + nt * 8 + 2 * t4;
                __half h0 = __float2half_rn((acc[mt][nt][0] + bv0) * sc);
                __half h1 = __float2half_rn((acc[mt][nt][1] + bv0) * sc);
                __half h2 = __float2half_rn((acc[mt][nt][2] + bv1) * sc);
                __half h3 = __float2half_rn((acc[mt][nt][3] + bv1) * sc);
                if (is_v) {
                    __half2 p01; p01.x = h0; p01.y = h1;
                    __half2 p23; p23.x = h2; p23.y = h3;
                    *(__half2*)&ep[(r)     * EPL + tl] = p01;
                    *(__half2*)&ep[(r + 8) * EPL + tl] = p23;
                } else {
                    ep[(tl)     * EPL + r]     = __half_as_ushort(h0);
                    ep[(tl + 1) * EPL + r]     = __half_as_ushort(h1);
                    ep[(tl)     * EPL + r + 8] = __half_as_ushort(h2);
                    ep[(tl + 1) * EPL + r + 8] = __half_as_ushort(h3);
                }
            }
        }
        __syncthreads();

        #pragma unroll
        for (int e = tid; e < 2048; e += 256) {
            const int a = e >> 4, c8 = e & 15;
            uint4 val = *(uint4*)&ep[a * EPL + c8 * 8];
            if (is_v) {
                const int ch = m0 - 512 + a;
                __half* gv = g_vh + ((size_t)(bb * 4 + (ch >> 6)) * 64 + (ch & 63)) * HWSZ
                           + n0 + c8 * 8;
                *(uint4*)gv = val;
            } else {
                const int gm = m0 + c8 * 8;
                const int tok = n0 + a;
                if (gm < 256) {
                    __half* gq = g_qh + ((size_t)(bb * 4 + (gm >> 6)) * HWSZ + tok) * 64
                               + (gm & 63);
                    *(uint4*)gq = val;
                } else {
                    __half* gk = g_kh + ((size_t)(bb * 4 + ((gm - 256) >> 6)) * HWSZ + tok) * 64
                               + (gm & 63);
                    *(uint4*)gk = val;
                }
            }
        }
    } else {
        #pragma unroll
        for (int mt = 0; mt < 2; mt++) {
            const int r0 = m0 + wm * 32 + mt * 16 + g4;
            const float bv0 = bias[r0], bv1 = bias[r0 + 8];
            #pragma unroll
            for (int nt = 0; nt < 8; nt++) {
                const int tok = n0 + wn * 64 + nt * 8 + 2 * t4;
                float v0 = acc[mt][nt][0] + bv0;
                float v1 = acc[mt][nt][1] + bv0;
                float v2 = acc[mt][nt][2] + bv1;
                float v3 = acc[mt][nt][3] + bv1;
                const float* rp = resid + ((size_t)bb * 256 + r0) * HWSZ + tok;
                float* op = out + ((size_t)bb * 256 + r0) * HWSZ + tok;
                float2 ra = *(const float2*)rp;
                float2 rb = *(const float2*)(rp + 8 * HWSZ);
                *(float2*)op              = make_float2(v0 + ra.x, v1 + ra.y);
                *(float2*)(op + 8 * HWSZ) = make_float2(v2 + rb.x, v3 + rb.y);
            }
        }
    }
}

// ============================================================
// fp16 flash attention: BM=256 (R12) + 3-stage cp.async pipeline.
// smem: K[3][64][36w] + V[3][64][36w] = 55296 B.
// ============================================================
#define LDW 36
#define KVW (64 * LDW)
#define ATTN_SMEM_BYTES (6 * KVW * 4)
#define ONE2 0x3C003C00u

__global__ void __launch_bounds__(256) attn_mma_kernel() {
    extern __shared__ uint32_t smw[];
    uint32_t* ks_base = smw;                 // 3 bufs
    uint32_t* vs_base = smw + 3 * KVW;       // 3 bufs

    const int tid = threadIdx.x, lane = tid & 31, wid = tid >> 5;
    const int g4 = lane >> 2, t4 = lane & 3;
    const int bh = blockIdx.y;
    const int bb = bh >> 2, hh = bh & 3;
    const int i0 = blockIdx.x * 256;
    const int wrow = wid * 32;

    const __half* qg = g_qh + (size_t)bh * HWSZ * 64;
    const __half* kg = g_kh + (size_t)bh * HWSZ * 64;
    const __half* vg = g_vh + (size_t)bh * 64 * HWSZ;

    const uint32_t ks_u = smem_u32(ks_base);
    const uint32_t vs_u = smem_u32(vs_base);

    const int lm_m = lane >> 3;
    const uint32_t lm_row = (uint32_t)(((lm_m >> 1) * 8) + (lane & 7));
    const uint32_t lm_kb  = (uint32_t)((lm_m & 1) * 16);

    uint32_t qf[2][4][4];
    #pragma unroll
    for (int mt = 0; mt < 2; mt++) {
        const __half* qr0 = qg + (size_t)(i0 + wrow + mt * 16 + g4) * 64;
        const __half* qr1 = qr0 + 8 * 64;
        #pragma unroll
        for (int kt = 0; kt < 4; kt++) {
            qf[mt][kt][0] = *(const uint32_t*)(qr0 + kt * 16 + 2 * t4);
            qf[mt][kt][1] = *(const uint32_t*)(qr1 + kt * 16 + 2 * t4);
            qf[mt][kt][2] = *(const uint32_t*)(qr0 + kt * 16 + 2 * t4 + 8);
            qf[mt][kt][3] = *(const uint32_t*)(qr1 + kt * 16 + 2 * t4 + 8);
        }
    }

    float of[2][9][4];
    #pragma unroll
    for (int mt = 0; mt < 2; mt++)
        #pragma unroll
        for (int nt = 0; nt < 9; nt++)
            #pragma unroll
            for (int i = 0; i < 4; i++) of[mt][nt][i] = 0.f;

    // prologue: tiles 0 and 1 into bufs 0,1 (two commit groups)
    #pragma unroll
    for (int t = 0; t < 2; t++) {
        const __half* kn = kg + (size_t)t * 64 * 64;
        const __half* vn = vg + t * 64;
        const uint32_t kd = ks_u + (t * KVW) * 4;
        const uint32_t vd = vs_u + (t * KVW) * 4;
        #pragma unroll 2
        for (int e = tid; e < 512; e += 256) {
            int r = e >> 3, c = e & 7;
            cp16(kd + (r * LDW) * 4 + c * 16, kn + (size_t)r * 64 + c * 8);
        }
        #pragma unroll 2
        for (int e = tid; e < 512; e += 256) {
            int r = e >> 3, c = e & 7;
            cp16(vd + (r * LDW) * 4 + c * 16, vn + (size_t)r * HWSZ + c * 8);
        }
        CP_COMMIT();
    }

    int buf = 0;
    for (int j = 0; j < 64; j++) {
        const uint32_t klm = ks_u + (buf * KVW + lm_row * LDW) * 4 + lm_kb;
        const uint32_t vlm = vs_u + (buf * KVW + lm_row * LDW) * 4 + lm_kb;

        if (j < 63) CP_WAIT1(); else CP_WAIT0();
        __syncthreads();

        if (j < 62) {
            int nb = buf + 2; if (nb >= 3) nb -= 3;
            const uint32_t kd = ks_u + (nb * KVW) * 4;
            const uint32_t vd = vs_u + (nb * KVW) * 4;
            const __half* kn = kg + (size_t)(j + 2) * 64 * 64;
            const __half* vn = vg + (j + 2) * 64;
            #pragma unroll 2
            for (int e = tid; e < 512; e += 256) {
                int r = e >> 3, c = e & 7;
                cp16(kd + (r * LDW) * 4 + c * 16, kn + (size_t)r * 64 + c * 8);
            }
            #pragma unroll 2
            for (int e = tid; e < 512; e += 256) {
                int r = e >> 3, c = e & 7;
                cp16(vd + (r * LDW) * 4 + c * 16, vn + (size_t)r * HWSZ + c * 8);
            }
            CP_COMMIT();
        }

        float sf[2][8][4];
        #pragma unroll
        for (int mt = 0; mt < 2; mt++)
            #pragma unroll
            for (int nt = 0; nt < 8; nt++)
                #pragma unroll
                for (int i = 0; i < 4; i++) sf[mt][nt][i] = 0.f;

        // ---- S_A ----
        #pragma unroll
        for (int kt = 0; kt < 4; kt++) {
            #pragma unroll
            for (int ntp = 0; ntp < 2; ntp++) {
                uint32_t br[4];
                ldsm4(br, klm + (ntp * 16 * LDW) * 4 + kt * 32);
                mma16(sf[0][2 * ntp],     qf[0][kt], br[0], br[1]);
                mma16(sf[1][2 * ntp],     qf[1][kt], br[0], br[1]);
                mma16(sf[0][2 * ntp + 1], qf[0][kt], br[2], br[3]);
                mma16(sf[1][2 * ntp + 1], qf[1][kt], br[2], br[3]);
            }
        }

        uint32_t pa[2][4][4];

        // ---- S_B || ex2_A ----
        #pragma unroll
        for (int kt = 0; kt < 4; kt++) {
            #pragma unroll
            for (int ntp = 2; ntp < 4; ntp++) {
                uint32_t br[4];
                ldsm4(br, klm + (ntp * 16 * LDW) * 4 + kt * 32);
                mma16(sf[0][2 * ntp],     qf[0][kt], br[0], br[1]);
                mma16(sf[1][2 * ntp],     qf[1][kt], br[0], br[1]);
                mma16(sf[0][2 * ntp + 1], qf[0][kt], br[2], br[3]);
                mma16(sf[1][2 * ntp + 1], qf[1][kt], br[2], br[3]);
            }
        }
        #pragma unroll
        for (int mt = 0; mt < 2; mt++)
            #pragma unroll
            for (int nt = 0; nt < 4; nt++) {
                float p0 = ex2f(sf[mt][nt][0]);
                float p1 = ex2f(sf[mt][nt][1]);
                float p2 = ex2f(sf[mt][nt][2]);
                float p3 = ex2f(sf[mt][nt][3]);
                pa[mt][nt >> 1][(nt & 1) * 2]     = pack_h2(p0, p1);
                pa[mt][nt >> 1][(nt & 1) * 2 + 1] = pack_h2(p2, p3);
            }

        // ---- PV_A || ex2_B ----
        #pragma unroll
        for (int kt = 0; kt < 2; kt++) {
            #pragma unroll
            for (int ntp = 0; ntp < 4; ntp++) {
                uint32_t br[4];
                ldsm4(br, vlm + (ntp * 16 * LDW) * 4 + kt * 32);
                mma16(of[0][2 * ntp],     pa[0][kt], br[0], br[1]);
                mma16(of[1][2 * ntp],     pa[1][kt], br[0], br[1]);
                mma16(of[0][2 * ntp + 1], pa[0][kt], br[2], br[3]);
                mma16(of[1][2 * ntp + 1], pa[1][kt], br[2], br[3]);
            }
            mma16(of[0][8], pa[0][kt], ONE2, ONE2);
            mma16(of[1][8], pa[1][kt], ONE2, ONE2);
        }
        #pragma unroll
        for (int mt = 0; mt < 2; mt++)
            #pragma unroll
            for (int nt = 4; nt < 8; nt++) {
                float p0 = ex2f(sf[mt][nt][0]);
                float p1 = ex2f(sf[mt][nt][1]);
                float p2 = ex2f(sf[mt][nt][2]);
                float p3 = ex2f(sf[mt][nt][3]);
                pa[mt][nt >> 1][(nt & 1) * 2]     = pack_h2(p0, p1);
                pa[mt][nt >> 1][(nt & 1) * 2 + 1] = pack_h2(p2, p3);
            }

        // ---- PV_B ----
        #pragma unroll
        for (int kt = 2; kt < 4; kt++) {
            #pragma unroll
            for (int ntp = 0; ntp < 4; ntp++) {
                uint32_t br[4];
                ldsm4(br, vlm + (ntp * 16 * LDW) * 4 + kt * 32);
                mma16(of[0][2 * ntp],     pa[0][kt], br[0], br[1]);
                mma16(of[1][2 * ntp],     pa[1][kt], br[0], br[1]);
                mma16(of[0][2 * ntp + 1], pa[0][kt], br[2], br[3]);
                mma16(of[1][2 * ntp + 1], pa[1][kt], br[2], br[3]);
            }
            mma16(of[0][8], pa[0][kt], ONE2, ONE2);
            mma16(of[1][8], pa[1][kt], ONE2, ONE2);
        }

        buf++; if (buf == 3) buf = 0;
    }

    #pragma unroll
    for (int mt = 0; mt < 2; mt++) {
        float inv0 = 1.f / of[mt][8][0];
        float inv1 = 1.f / of[mt][8][2];
        int tok = i0 + wrow + mt * 16 + g4;
        __half* d0 = g_oh + ((size_t)bb * HWSZ + tok) * 256 + hh * 64;
        __half* d1 = d0 + 8 * 256;
        #pragma unroll
        for (int nt = 0; nt < 8; nt++) {
            int ch = nt * 8 + 2 * t4;
            *(__half2*)(d0 + ch) = __floats2half2_rn(of[mt][nt][0] * inv0,
                                                     of[mt][nt][1] * inv0);
            *(__half2*)(d1 + ch) = __floats2half2_rn(of[mt][nt][2] * inv1,
                                                     of[mt][nt][3] * inv1);
        }
    }
}

// ============================================================
extern "C" void kernel_launch(void* const* d_in, const int* in_sizes, int n_in,
                              void* d_out, int out_size) {
    const float* x      = (const float*)d_in[0];
    const float* norm_w = (const float*)d_in[1];
    const float* norm_b = (const float*)d_in[2];
    const float* qkv_w  = (const float*)d_in[3];
    const float* qkv_b  = (const float*)d_in[4];
    const float* proj_w = (const float*)d_in[5];
    const float* proj_b = (const float*)d_in[6];
    float* out = (float*)d_out;

    void *pht, *poh, *pwq, *pwp;
    cudaGetSymbolAddress(&pht, g_ht);
    cudaGetSymbolAddress(&poh, g_oh);
    cudaGetSymbolAddress(&pwq, g_wqkv);
    cudaGetSymbolAddress(&pwp, g_wproj);

    cudaFuncSetAttribute(gemm_h_kernel<768, true>,
                         cudaFuncAttributeMaxDynamicSharedMemorySize, GEMM_SMEM_BYTES);
    cudaFuncSetAttribute(gemm_h_kernel<256, false>,
                         cudaFuncAttributeMaxDynamicSharedMemorySize, GEMM_SMEM_BYTES);
    cudaFuncSetAttribute(attn_mma_kernel,
                         cudaFuncAttributeMaxDynamicSharedMemorySize, ATTN_SMEM_BYTES);

    gn_partial_conv_kernel<<<832, 256>>>(x, qkv_w, proj_w);
    gn_final_kernel<<<1, 32>>>();
    gn_norm_kernel<<<dim3(HWSZ / 128, 32), 256>>>(x, norm_w, norm_b);

    gemm_h_kernel<768, true><<<dim3(HWSZ / 128, 768 / 128, BATCH), 256, GEMM_SMEM_BYTES>>>(
        (const __half*)pwq, (const __half*)pht, qkv_b, nullptr, nullptr);

    attn_mma_kernel<<<dim3(HWSZ / 256, NBH), 256, ATTN_SMEM_BYTES>>>();

    gemm_h_kernel<256, false><<<dim3(HWSZ / 128, 256 / 128, BATCH), 256, GEMM_SMEM_BYTES>>>(
        (const __half*)pwp, (const __half*)poh, proj_b, x, out);
}

// round 15
// speedup vs baseline: 1.0420x; 1.0420x over previous
#include <cuda_runtime.h>
#include <cuda_fp16.h>
#include <math.h>
#include <stdint.h>

#define CC 256
#define HWSZ 4096
#define BATCH 4
#define NHEAD 4
#define NBH 16

// -------- scratch (device globals; no allocations allowed) --------
__device__ __half g_ht [(size_t)BATCH * HWSZ * CC];      // normalized input, [b][tok][c] half
__device__ __half g_oh [(size_t)BATCH * HWSZ * CC];      // attention out, [b][tok][c] half
__device__ __half g_qh [(size_t)NBH * HWSZ * 64];        // q: [bh][tok][c] half, *0.125*log2e
__device__ __half g_kh [(size_t)NBH * HWSZ * 64];        // k: [bh][tok][c] half
__device__ __half g_vh [(size_t)NBH * 64 * HWSZ];        // v: [bh][c][tok] half
__device__ __half g_wqkv[768 * 256];                     // fp16 weights
__device__ __half g_wproj[256 * 256];
__device__ float2 g_part[512];                           // per-slice (sum, sumsq)

// ============================================================
// helpers (sm_80-baseline PTX only)
// ============================================================
__device__ __forceinline__ uint32_t smem_u32(const void* p) {
    uint32_t a;
    asm("{ .reg .u64 t; cvta.to.shared.u64 t, %1; cvt.u32.u64 %0, t; }" : "=r"(a) : "l"(p));
    return a;
}
__device__ __forceinline__ float ex2f(float x) {
    float r;
    asm("ex2.approx.ftz.f32 %0, %1;" : "=f"(r) : "f"(x));
    return r;
}
__device__ __forceinline__ uint32_t pack_h2(float lo, float hi) {
    uint32_t d;
    asm("cvt.rn.f16x2.f32 %0, %1, %2;" : "=r"(d) : "f"(hi), "f"(lo));
    return d;
}
__device__ __forceinline__ void cp16(uint32_t dst, const void* src) {
    asm volatile("cp.async.cg.shared.global [%0], [%1], 16;" :: "r"(dst), "l"(src) : "memory");
}
#define CP_COMMIT()  asm volatile("cp.async.commit_group;" ::: "memory")
#define CP_WAIT0()   asm volatile("cp.async.wait_group 0;" ::: "memory")

__device__ __forceinline__ void ldsm4(uint32_t r[4], uint32_t addr) {
    asm volatile("ldmatrix.sync.aligned.m8n8.x4.shared.b16 {%0,%1,%2,%3}, [%4];"
        : "=r"(r[0]), "=r"(r[1]), "=r"(r[2]), "=r"(r[3]) : "r"(addr));
}

// fp16 m16n8k16, fp32 accum
__device__ __forceinline__ void mma16(float c[4], const uint32_t a_[4], uint32_t b0, uint32_t b1) {
    asm volatile("mma.sync.aligned.m16n8k16.row.col.f32.f16.f16.f32 "
        "{%0,%1,%2,%3}, {%4,%5,%6,%7}, {%8,%9}, {%0,%1,%2,%3};"
        : "+f"(c[0]), "+f"(c[1]), "+f"(c[2]), "+f"(c[3])
        : "r"(a_[0]), "r"(a_[1]), "r"(a_[2]), "r"(a_[3]),
          "r"(b0), "r"(b1));
}

// ============================================================
// GroupNorm partial stats (blocks 0..511, slices of 8192 floats)
// + weight fp16 convert (blocks 512..831). One launch.
// ============================================================
__global__ void gn_partial_conv_kernel(const float* __restrict__ x,
                                       const float* __restrict__ qkv_w,
                                       const float* __restrict__ proj_w) {
    const int bid = blockIdx.x;
    const int tid = threadIdx.x;
    if (bid < 512) {
        const float* xp = x + (size_t)bid * 8192;
        float s = 0.f, ss = 0.f;
        #pragma unroll 8
        for (int i = tid * 4; i < 8192; i += 1024) {
            float4 v = *(const float4*)(xp + i);
            s  += v.x + v.y + v.z + v.w;
            ss += v.x * v.x + v.y * v.y + v.z * v.z + v.w * v.w;
        }
        __shared__ float rs[256], rss[256];
        rs[tid] = s; rss[tid] = ss;
        __syncthreads();
        for (int o = 128; o > 0; o >>= 1) {
            if (tid < o) { rs[tid] += rs[tid + o]; rss[tid] += rss[tid + o]; }
            __syncthreads();
        }
        if (tid == 0) g_part[bid] = make_float2(rs[0], rss[0]);
    } else {
        int i = ((bid - 512) * 256 + tid) * 4;
        float4 v;
        if (i < 768 * 256) {
            v = *(const float4*)(qkv_w + i);
            *(__half2*)(g_wqkv + i)     = __floats2half2_rn(v.x, v.y);
            *(__half2*)(g_wqkv + i + 2) = __floats2half2_rn(v.z, v.w);
        } else {
            int k = i - 768 * 256;
            v = *(const float4*)(proj_w + k);
            *(__half2*)(g_wproj + k)     = __floats2half2_rn(v.x, v.y);
            *(__half2*)(g_wproj + k + 2) = __floats2half2_rn(v.z, v.w);
        }
    }
}

// normalize + transpose + fp16; stats finalized in-block (no gn_final launch)
__global__ void gn_norm_kernel(const float* __restrict__ x,
                               const float* __restrict__ w,
                               const float* __restrict__ b) {
    __shared__ float tile[32][129];
    __shared__ float2 sst;
    const int t0 = blockIdx.x * 128;
    const int bg = blockIdx.y;
    const int bb = bg >> 3, gg = bg & 7;
    const int tid = threadIdx.x;

    if (tid == 0) {
        float s = 0.f, ss = 0.f;
        #pragma unroll
        for (int i = 0; i < 16; i++) {
            float2 p = g_part[bg * 16 + i];
            s += p.x; ss += p.y;
        }
        float mean = s / 131072.f;
        float var  = ss / 131072.f - mean * mean;
        sst = make_float2(mean, rsqrtf(var + 1e-5f));
    }

    const float* xp = x + ((size_t)bb * 256 + gg * 32) * HWSZ + t0;
    #pragma unroll 4
    for (int i = tid; i < 1024; i += 256) {
        int row = i >> 5, c4 = i & 31;
        float4 v = *(const float4*)(xp + (size_t)row * HWSZ + c4 * 4);
        tile[row][c4 * 4 + 0] = v.x;
        tile[row][c4 * 4 + 1] = v.y;
        tile[row][c4 * 4 + 2] = v.z;
        tile[row][c4 * 4 + 3] = v.w;
    }
    __syncthreads();
    float2 st = sst;

    const int tok = tid >> 1, seg = tid & 1;
    __half hv[16];
    #pragma unroll
    for (int i = 0; i < 16; i++) {
        int cc = seg * 16 + i;
        int c = gg * 32 + cc;
        float sc = st.y * w[c];
        float of = b[c] - st.x * sc;
        hv[i] = __float2half_rn(tile[cc][tok] * sc + of);
    }
    __half* dst = g_ht + ((size_t)bb * HWSZ + t0 + tok) * 256 + gg * 32 + seg * 16;
    *(uint4*)dst       = *(uint4*)hv;
    *(uint4*)(dst + 8) = *(uint4*)(hv + 8);
}

// ============================================================
// fp16 tensor-core GEMM (R12 proven config).
// ============================================================
#define LDWH 20
#define TILEW (128 * LDWH)
#define GEMM_SMEM_BYTES (4 * TILEW * 4)
#define QSCALE 0.18033688011112042f
#define EPL 136

template<int M_TOTAL, bool QKV_MODE>
__global__ void __launch_bounds__(256, 2) gemm_h_kernel(
        const __half* __restrict__ A,
        const __half* __restrict__ Bt,
        const float* __restrict__ bias,
        const float* __restrict__ resid,
        float* __restrict__ out) {
    extern __shared__ uint32_t sw[];
    uint32_t* a_s = sw;
    uint32_t* b_s = sw + 2 * TILEW;
    const uint32_t a_u = smem_u32(a_s);
    const uint32_t b_u = smem_u32(b_s);

    const int tid = threadIdx.x, lane = tid & 31, wid = tid >> 5;
    const int g4 = lane >> 2, t4 = lane & 3;
    const int wm = wid >> 1, wn = wid & 1;
    const int bb = blockIdx.z;
    const int m0 = blockIdx.y * 128;
    const int n0 = blockIdx.x * 128;
    const __half* Bp = Bt + (size_t)bb * HWSZ * 256 + (size_t)n0 * 256;

    float acc[2][8][4];
    #pragma unroll
    for (int mt = 0; mt < 2; mt++)
        #pragma unroll
        for (int nt = 0; nt < 8; nt++)
            #pragma unroll
            for (int i = 0; i < 4; i++) acc[mt][nt][i] = 0.f;

    #pragma unroll 2
    for (int e = tid; e < 512; e += 256) {
        int r = e >> 2, c8 = e & 3;
        cp16(a_u + (r * LDWH + c8 * 4) * 4, A + (size_t)(m0 + r) * 256 + c8 * 8);
    }
    #pragma unroll 2
    for (int e = tid; e < 512; e += 256) {
        int r = e >> 2, c8 = e & 3;
        cp16(b_u + (r * LDWH + c8 * 4) * 4, Bp + (size_t)r * 256 + c8 * 8);
    }
    CP_COMMIT();

    for (int j = 0; j < 8; j++) {
        const int buf = j & 1;
        const uint32_t* at = a_s + buf * TILEW;
        const uint32_t* bt = b_s + buf * TILEW;

        CP_WAIT0();
        __syncthreads();

        if (j < 7) {
            const uint32_t ad = a_u + ((buf ^ 1) * TILEW) * 4;
            const uint32_t bd = b_u + ((buf ^ 1) * TILEW) * 4;
            const int k0 = (j + 1) * 32;
            #pragma unroll 2
            for (int e = tid; e < 512; e += 256) {
                int r = e >> 2, c8 = e & 3;
                cp16(ad + (r * LDWH + c8 * 4) * 4, A + (size_t)(m0 + r) * 256 + k0 + c8 * 8);
            }
            #pragma unroll 2
            for (int e = tid; e < 512; e += 256) {
                int r = e >> 2, c8 = e & 3;
                cp16(bd + (r * LDWH + c8 * 4) * 4, Bp + (size_t)r * 256 + k0 + c8 * 8);
            }
            CP_COMMIT();
        }

        #pragma unroll
        for (int kt = 0; kt < 2; kt++) {
            uint32_t af[2][4];
            #pragma unroll
            for (int mt = 0; mt < 2; mt++) {
                const uint32_t* ap = at + (wm * 32 + mt * 16 + g4) * LDWH + kt * 8 + t4;
                af[mt][0] = ap[0];
                af[mt][1] = ap[8 * LDWH];
                af[mt][2] = ap[4];
                af[mt][3] = ap[8 * LDWH + 4];
            }
            const uint32_t* bp = bt + (wn * 64 + g4) * LDWH + kt * 8 + t4;
            #pragma unroll
            for (int nt = 0; nt < 8; nt++) {
                uint32_t b0 = bp[nt * 8 * LDWH];
                uint32_t b1 = bp[nt * 8 * LDWH + 4];
                mma16(acc[0][nt], af[0], b0, b1);
                mma16(acc[1][nt], af[1], b0, b1);
            }
        }
        __syncthreads();
    }

    // ---- epilogue ----
    if (QKV_MODE) {
        uint16_t* ep = (uint16_t*)sw;
        const bool is_v = (m0 >= 512);
        const float sc = (m0 < 256) ? QSCALE : 1.0f;

        #pragma unroll
        for (int mt = 0; mt < 2; mt++) {
            const int r = wm * 32 + mt * 16 + g4;
            const float bv0 = bias[m0 + r], bv1 = bias[m0 + r + 8];
            #pragma unroll
            for (int nt = 0; nt < 8; nt++) {
                const int tl = wn * 64 + nt * 8 + 2 * t4;
                __half h0 = __float2half_rn((acc[mt][nt][0] + bv0) * sc);
                __half h1 = __float2half_rn((acc[mt][nt][1] + bv0) * sc);
                __half h2 = __float2half_rn((acc[mt][nt][2] + bv1) * sc);
                __half h3 = __float2half_rn((acc[mt][nt][3] + bv1) * sc);
                if (is_v) {
                    __half2 p01; p01.x = h0; p01.y = h1;
                    __half2 p23; p23.x = h2; p23.y = h3;
                    *(__half2*)&ep[(r)     * EPL + tl] = p01;
                    *(__half2*)&ep[(r + 8) * EPL + tl] = p23;
                } else {
                    ep[(tl)     * EPL + r]     = __half_as_ushort(h0);
                    ep[(tl + 1) * EPL + r]     = __half_as_ushort(h1);
                    ep[(tl)     * EPL + r + 8] = __half_as_ushort(h2);
                    ep[(tl + 1) * EPL + r + 8] = __half_as_ushort(h3);
                }
            }
        }
        __syncthreads();

        #pragma unroll
        for (int e = tid; e < 2048; e += 256) {
            const int a = e >> 4, c8 = e & 15;
            uint4 val = *(uint4*)&ep[a * EPL + c8 * 8];
            if (is_v) {
                const int ch = m0 - 512 + a;
                __half* gv = g_vh + ((size_t)(bb * 4 + (ch >> 6)) * 64 + (ch & 63)) * HWSZ
                           + n0 + c8 * 8;
                *(uint4*)gv = val;
            } else {
                const int gm = m0 + c8 * 8;
                const int tok = n0 + a;
                if (gm < 256) {
                    __half* gq = g_qh + ((size_t)(bb * 4 + (gm >> 6)) * HWSZ + tok) * 64
                               + (gm & 63);
                    *(uint4*)gq = val;
                } else {
                    __half* gk = g_kh + ((size_t)(bb * 4 + ((gm - 256) >> 6)) * HWSZ + tok) * 64
                               + (gm & 63);
                    *(uint4*)gk = val;
                }
            }
        }
    } else {
        #pragma unroll
        for (int mt = 0; mt < 2; mt++) {
            const int r0 = m0 + wm * 32 + mt * 16 + g4;
            const float bv0 = bias[r0], bv1 = bias[r0 + 8];
            #pragma unroll
            for (int nt = 0; nt < 8; nt++) {
                const int tok = n0 + wn * 64 + nt * 8 + 2 * t4;
                float v0 = acc[mt][nt][0] + bv0;
                float v1 = acc[mt][nt][1] + bv0;
                float v2 = acc[mt][nt][2] + bv1;
                float v3 = acc[mt][nt][3] + bv1;
                const float* rp = resid + ((size_t)bb * 256 + r0) * HWSZ + tok;
                float* op = out + ((size_t)bb * 256 + r0) * HWSZ + tok;
                float2 ra = *(const float2*)rp;
                float2 rb = *(const float2*)(rp + 8 * HWSZ);
                *(float2*)op              = make_float2(v0 + ra.x, v1 + ra.y);
                *(float2*)(op + 8 * HWSZ) = make_float2(v2 + rb.x, v3 + rb.y);
            }
        }
    }
}

// ============================================================
// fp16 flash attention: BM=256, 2-stage (exact R12 best config).
// ============================================================
#define LDW 36
#define KVW (64 * LDW)
#define ATTN_SMEM_BYTES (4 * KVW * 4)
#define ONE2 0x3C003C00u

__global__ void __launch_bounds__(256) attn_mma_kernel() {
    extern __shared__ uint32_t smw[];
    uint32_t* ks_base = smw;
    uint32_t* vs_base = smw + 2 * KVW;

    const int tid = threadIdx.x, lane = tid & 31, wid = tid >> 5;
    const int g4 = lane >> 2, t4 = lane & 3;
    const int bh = blockIdx.y;
    const int bb = bh >> 2, hh = bh & 3;
    const int i0 = blockIdx.x * 256;
    const int wrow = wid * 32;

    const __half* qg = g_qh + (size_t)bh * HWSZ * 64;
    const __half* kg = g_kh + (size_t)bh * HWSZ * 64;
    const __half* vg = g_vh + (size_t)bh * 64 * HWSZ;

    const uint32_t ks_u = smem_u32(ks_base);
    const uint32_t vs_u = smem_u32(vs_base);

    const int lm_m = lane >> 3;
    const uint32_t lm_row = (uint32_t)(((lm_m >> 1) * 8) + (lane & 7));
    const uint32_t lm_kb  = (uint32_t)((lm_m & 1) * 16);

    uint32_t qf[2][4][4];
    #pragma unroll
    for (int mt = 0; mt < 2; mt++) {
        const __half* qr0 = qg + (size_t)(i0 + wrow + mt * 16 + g4) * 64;
        const __half* qr1 = qr0 + 8 * 64;
        #pragma unroll
        for (int kt = 0; kt < 4; kt++) {
            qf[mt][kt][0] = *(const uint32_t*)(qr0 + kt * 16 + 2 * t4);
            qf[mt][kt][1] = *(const uint32_t*)(qr1 + kt * 16 + 2 * t4);
            qf[mt][kt][2] = *(const uint32_t*)(qr0 + kt * 16 + 2 * t4 + 8);
            qf[mt][kt][3] = *(const uint32_t*)(qr1 + kt * 16 + 2 * t4 + 8);
        }
    }

    float of[2][9][4];
    #pragma unroll
    for (int mt = 0; mt < 2; mt++)
        #pragma unroll
        for (int nt = 0; nt < 9; nt++)
            #pragma unroll
            for (int i = 0; i < 4; i++) of[mt][nt][i] = 0.f;

    #pragma unroll 2
    for (int e = tid; e < 512; e += 256) {
        int r = e >> 3, c = e & 7;
        cp16(ks_u + (r * LDW) * 4 + c * 16, kg + (size_t)r * 64 + c * 8);
    }
    #pragma unroll 2
    for (int e = tid; e < 512; e += 256) {
        int r = e >> 3, c = e & 7;
        cp16(vs_u + (r * LDW) * 4 + c * 16, vg + (size_t)r * HWSZ + c * 8);
    }
    CP_COMMIT();

    for (int j = 0; j < 64; j++) {
        const int buf = j & 1;
        const uint32_t klm = ks_u + (buf * KVW + lm_row * LDW) * 4 + lm_kb;
        const uint32_t vlm = vs_u + (buf * KVW + lm_row * LDW) * 4 + lm_kb;

        CP_WAIT0();
        __syncthreads();

        if (j < 63) {
            const uint32_t kd = ks_u + ((buf ^ 1) * KVW) * 4;
            const uint32_t vd = vs_u + ((buf ^ 1) * KVW) * 4;
            const __half* kn = kg + (size_t)(j + 1) * 64 * 64;
            const __half* vn = vg + (j + 1) * 64;
            #pragma unroll 2
            for (int e = tid; e < 512; e += 256) {
                int r = e >> 3, c = e & 7;
                cp16(kd + (r * LDW) * 4 + c * 16, kn + (size_t)r * 64 + c * 8);
            }
            #pragma unroll 2
            for (int e = tid; e < 512; e += 256) {
                int r = e >> 3, c = e & 7;
                cp16(vd + (r * LDW) * 4 + c * 16, vn + (size_t)r * HWSZ + c * 8);
            }
            CP_COMMIT();
        }

        float sf[2][8][4];
        #pragma unroll
        for (int mt = 0; mt < 2; mt++)
            #pragma unroll
            for (int nt = 0; nt < 8; nt++)
                #pragma unroll
                for (int i = 0; i < 4; i++) sf[mt][nt][i] = 0.f;

        // ---- S_A ----
        #pragma unroll
        for (int kt = 0; kt < 4; kt++) {
            #pragma unroll
            for (int ntp = 0; ntp < 2; ntp++) {
                uint32_t br[4];
                ldsm4(br, klm + (ntp * 16 * LDW) * 4 + kt * 32);
                mma16(sf[0][2 * ntp],     qf[0][kt], br[0], br[1]);
                mma16(sf[1][2 * ntp],     qf[1][kt], br[0], br[1]);
                mma16(sf[0][2 * ntp + 1], qf[0][kt], br[2], br[3]);
                mma16(sf[1][2 * ntp + 1], qf[1][kt], br[2], br[3]);
            }
        }

        uint32_t pa[2][4][4];

        // ---- S_B || ex2_A ----
        #pragma unroll
        for (int kt = 0; kt < 4; kt++) {
            #pragma unroll
            for (int ntp = 2; ntp < 4; ntp++) {
                uint32_t br[4];
                ldsm4(br, klm + (ntp * 16 * LDW) * 4 + kt * 32);
                mma16(sf[0][2 * ntp],     qf[0][kt], br[0], br[1]);
                mma16(sf[1][2 * ntp],     qf[1][kt], br[0], br[1]);
                mma16(sf[0][2 * ntp + 1], qf[0][kt], br[2], br[3]);
                mma16(sf[1][2 * ntp + 1], qf[1][kt], br[2], br[3]);
            }
        }
        #pragma unroll
        for (int mt = 0; mt < 2; mt++)
            #pragma unroll
            for (int nt = 0; nt < 4; nt++) {
                float p0 = ex2f(sf[mt][nt][0]);
                float p1 = ex2f(sf[mt][nt][1]);
                float p2 = ex2f(sf[mt][nt][2]);
                float p3 = ex2f(sf[mt][nt][3]);
                pa[mt][nt >> 1][(nt & 1) * 2]     = pack_h2(p0, p1);
                pa[mt][nt >> 1][(nt & 1) * 2 + 1] = pack_h2(p2, p3);
            }

        // ---- PV_A || ex2_B ----
        #pragma unroll
        for (int kt = 0; kt < 2; kt++) {
            #pragma unroll
            for (int ntp = 0; ntp < 4; ntp++) {
                uint32_t br[4];
                ldsm4(br, vlm + (ntp * 16 * LDW) * 4 + kt * 32);
                mma16(of[0][2 * ntp],     pa[0][kt], br[0], br[1]);
                mma16(of[1][2 * ntp],     pa[1][kt], br[0], br[1]);
                mma16(of[0][2 * ntp + 1], pa[0][kt], br[2], br[3]);
                mma16(of[1][2 * ntp + 1], pa[1][kt], br[2], br[3]);
            }
            mma16(of[0][8], pa[0][kt], ONE2, ONE2);
            mma16(of[1][8], pa[1][kt], ONE2, ONE2);
        }
        #pragma unroll
        for (int mt = 0; mt < 2; mt++)
            #pragma unroll
            for (int nt = 4; nt < 8; nt++) {
                float p0 = ex2f(sf[mt][nt][0]);
                float p1 = ex2f(sf[mt][nt][1]);
                float p2 = ex2f(sf[mt][nt][2]);
                float p3 = ex2f(sf[mt][nt][3]);
                pa[mt][nt >> 1][(nt & 1) * 2]     = pack_h2(p0, p1);
                pa[mt][nt >> 1][(nt & 1) * 2 + 1] = pack_h2(p2, p3);
            }

        // ---- PV_B ----
        #pragma unroll
        for (int kt = 2; kt < 4; kt++) {
            #pragma unroll
            for (int ntp = 0; ntp < 4; ntp++) {
                uint32_t br[4];
                ldsm4(br, vlm + (ntp * 16 * LDW) * 4 + kt * 32);
                mma16(of[0][2 * ntp],     pa[0][kt], br[0], br[1]);
                mma16(of[1][2 * ntp],     pa[1][kt], br[0], br[1]);
                mma16(of[0][2 * ntp + 1], pa[0][kt], br[2], br[3]);
                mma16(of[1][2 * ntp + 1], pa[1][kt], br[2], br[3]);
            }
            mma16(of[0][8], pa[0][kt], ONE2, ONE2);
            mma16(of[1][8], pa[1][kt], ONE2, ONE2);
        }
    }

    #pragma unroll
    for (int mt = 0; mt < 2; mt++) {
        float inv0 = 1.f / of[mt][8][0];
        float inv1 = 1.f / of[mt][8][2];
        int tok = i0 + wrow + mt * 16 + g4;
        __half* d0 = g_oh + ((size_t)bb * HWSZ + tok) * 256 + hh * 64;
        __half* d1 = d0 + 8 * 256;
        #pragma unroll
        for (int nt = 0; nt < 8; nt++) {
            int ch = nt * 8 + 2 * t4;
            *(__half2*)(d0 + ch) = __floats2half2_rn(of[mt][nt][0] * inv0,
                                                     of[mt][nt][1] * inv0);
            *(__half2*)(d1 + ch) = __floats2half2_rn(of[mt][nt][2] * inv1,
                                                     of[mt][nt][3] * inv1);
        }
    }
}

// ============================================================
extern "C" void kernel_launch(void* const* d_in, const int* in_sizes, int n_in,
                              void* d_out, int out_size) {
    const float* x      = (const float*)d_in[0];
    const float* norm_w = (const float*)d_in[1];
    const float* norm_b = (const float*)d_in[2];
    const float* qkv_w  = (const float*)d_in[3];
    const float* qkv_b  = (const float*)d_in[4];
    const float* proj_w = (const float*)d_in[5];
    const float* proj_b = (const float*)d_in[6];
    float* out = (float*)d_out;

    void *pht, *poh, *pwq, *pwp;
    cudaGetSymbolAddress(&pht, g_ht);
    cudaGetSymbolAddress(&poh, g_oh);
    cudaGetSymbolAddress(&pwq, g_wqkv);
    cudaGetSymbolAddress(&pwp, g_wproj);

    cudaFuncSetAttribute(gemm_h_kernel<768, true>,
                         cudaFuncAttributeMaxDynamicSharedMemorySize, GEMM_SMEM_BYTES);
    cudaFuncSetAttribute(gemm_h_kernel<256, false>,
                         cudaFuncAttributeMaxDynamicSharedMemorySize, GEMM_SMEM_BYTES);
    cudaFuncSetAttribute(attn_mma_kernel,
                         cudaFuncAttributeMaxDynamicSharedMemorySize, ATTN_SMEM_BYTES);

    gn_partial_conv_kernel<<<832, 256>>>(x, qkv_w, proj_w);
    gn_norm_kernel<<<dim3(HWSZ / 128, 32), 256>>>(x, norm_w, norm_b);

    gemm_h_kernel<768, true><<<dim3(HWSZ / 128, 768 / 128, BATCH), 256, GEMM_SMEM_BYTES>>>(
        (const __half*)pwq, (const __half*)pht, qkv_b, nullptr, nullptr);

    attn_mma_kernel<<<dim3(HWSZ / 256, NBH), 256, ATTN_SMEM_BYTES>>>();

    gemm_h_kernel<256, false><<<dim3(HWSZ / 128, 256 / 128, BATCH), 256, GEMM_SMEM_BYTES>>>(
        (const __half*)pwp, (const __half*)poh, proj_b, x, out);
}

// round 16
// speedup vs baseline: 1.0499x; 1.0076x over previous
#include <cuda_runtime.h>
#include <cuda_fp16.h>
#include <math.h>
#include <stdint.h>

#define CC 256
#define HWSZ 4096
#define BATCH 4
#define NHEAD 4
#define NBH 16

// -------- scratch (device globals; no allocations allowed) --------
__device__ __half g_ht [(size_t)BATCH * HWSZ * CC];      // normalized input, [b][tok][c] half
__device__ __half g_oh [(size_t)BATCH * HWSZ * CC];      // attention out, [b][tok][c] half
__device__ __half g_qh [(size_t)NBH * HWSZ * 64];        // q: [bh][tok][c] half, *0.125*log2e
__device__ __half g_kh [(size_t)NBH * HWSZ * 64];        // k: [bh][tok][c] half
__device__ __half g_vh [(size_t)NBH * 64 * HWSZ];        // v: [bh][c][tok] half
__device__ __half g_wqkv[768 * 256];                     // fp16 weights
__device__ __half g_wproj[256 * 256];
__device__ float2 g_part[512];                           // per-slice (sum, sumsq)

// ============================================================
// helpers (sm_80-baseline PTX only)
// ============================================================
__device__ __forceinline__ uint32_t smem_u32(const void* p) {
    uint32_t a;
    asm("{ .reg .u64 t; cvta.to.shared.u64 t, %1; cvt.u32.u64 %0, t; }" : "=r"(a) : "l"(p));
    return a;
}
__device__ __forceinline__ float ex2f(float x) {
    float r;
    asm("ex2.approx.ftz.f32 %0, %1;" : "=f"(r) : "f"(x));
    return r;
}
__device__ __forceinline__ uint32_t pack_h2(float lo, float hi) {
    uint32_t d;
    asm("cvt.rn.f16x2.f32 %0, %1, %2;" : "=r"(d) : "f"(hi), "f"(lo));
    return d;
}
__device__ __forceinline__ void cp16(uint32_t dst, const void* src) {
    asm volatile("cp.async.cg.shared.global [%0], [%1], 16;" :: "r"(dst), "l"(src) : "memory");
}
#define CP_COMMIT()  asm volatile("cp.async.commit_group;" ::: "memory")
#define CP_WAIT0()   asm volatile("cp.async.wait_group 0;" ::: "memory")
#define CP_WAIT1()   asm volatile("cp.async.wait_group 1;" ::: "memory")

__device__ __forceinline__ void ldsm4(uint32_t r[4], uint32_t addr) {
    asm volatile("ldmatrix.sync.aligned.m8n8.x4.shared.b16 {%0,%1,%2,%3}, [%4];"
        : "=r"(r[0]), "=r"(r[1]), "=r"(r[2]), "=r"(r[3]) : "r"(addr));
}

// fp16 m16n8k16, fp32 accum
__device__ __forceinline__ void mma16(float c[4], const uint32_t a_[4], uint32_t b0, uint32_t b1) {
    asm volatile("mma.sync.aligned.m16n8k16.row.col.f32.f16.f16.f32 "
        "{%0,%1,%2,%3}, {%4,%5,%6,%7}, {%8,%9}, {%0,%1,%2,%3};"
        : "+f"(c[0]), "+f"(c[1]), "+f"(c[2]), "+f"(c[3])
        : "r"(a_[0]), "r"(a_[1]), "r"(a_[2]), "r"(a_[3]),
          "r"(b0), "r"(b1));
}

// ============================================================
// GroupNorm partial stats (blocks 0..511, slices of 8192 floats)
// + weight fp16 convert (blocks 512..831). One launch.
// ============================================================
__global__ void gn_partial_conv_kernel(const float* __restrict__ x,
                                       const float* __restrict__ qkv_w,
                                       const float* __restrict__ proj_w) {
    const int bid = blockIdx.x;
    const int tid = threadIdx.x;
    if (bid < 512) {
        const float* xp = x + (size_t)bid * 8192;
        float s = 0.f, ss = 0.f;
        #pragma unroll 8
        for (int i = tid * 4; i < 8192; i += 1024) {
            float4 v = *(const float4*)(xp + i);
            s  += v.x + v.y + v.z + v.w;
            ss += v.x * v.x + v.y * v.y + v.z * v.z + v.w * v.w;
        }
        __shared__ float rs[256], rss[256];
        rs[tid] = s; rss[tid] = ss;
        __syncthreads();
        for (int o = 128; o > 0; o >>= 1) {
            if (tid < o) { rs[tid] += rs[tid + o]; rss[tid] += rss[tid + o]; }
            __syncthreads();
        }
        if (tid == 0) g_part[bid] = make_float2(rs[0], rss[0]);
    } else {
        int i = ((bid - 512) * 256 + tid) * 4;
        float4 v;
        if (i < 768 * 256) {
            v = *(const float4*)(qkv_w + i);
            *(__half2*)(g_wqkv + i)     = __floats2half2_rn(v.x, v.y);
            *(__half2*)(g_wqkv + i + 2) = __floats2half2_rn(v.z, v.w);
        } else {
            int k = i - 768 * 256;
            v = *(const float4*)(proj_w + k);
            *(__half2*)(g_wproj + k)     = __floats2half2_rn(v.x, v.y);
            *(__half2*)(g_wproj + k + 2) = __floats2half2_rn(v.z, v.w);
        }
    }
}

// normalize + transpose + fp16; stats finalized in-block
__global__ void gn_norm_kernel(const float* __restrict__ x,
                               const float* __restrict__ w,
                               const float* __restrict__ b) {
    __shared__ float tile[32][129];
    __shared__ float2 sst;
    const int t0 = blockIdx.x * 128;
    const int bg = blockIdx.y;
    const int bb = bg >> 3, gg = bg & 7;
    const int tid = threadIdx.x;

    if (tid == 0) {
        float s = 0.f, ss = 0.f;
        #pragma unroll
        for (int i = 0; i < 16; i++) {
            float2 p = g_part[bg * 16 + i];
            s += p.x; ss += p.y;
        }
        float mean = s / 131072.f;
        float var  = ss / 131072.f - mean * mean;
        sst = make_float2(mean, rsqrtf(var + 1e-5f));
    }

    const float* xp = x + ((size_t)bb * 256 + gg * 32) * HWSZ + t0;
    #pragma unroll 4
    for (int i = tid; i < 1024; i += 256) {
        int row = i >> 5, c4 = i & 31;
        float4 v = *(const float4*)(xp + (size_t)row * HWSZ + c4 * 4);
        tile[row][c4 * 4 + 0] = v.x;
        tile[row][c4 * 4 + 1] = v.y;
        tile[row][c4 * 4 + 2] = v.z;
        tile[row][c4 * 4 + 3] = v.w;
    }
    __syncthreads();
    float2 st = sst;

    const int tok = tid >> 1, seg = tid & 1;
    __half hv[16];
    #pragma unroll
    for (int i = 0; i < 16; i++) {
        int cc = seg * 16 + i;
        int c = gg * 32 + cc;
        float sc = st.y * w[c];
        float of = b[c] - st.x * sc;
        hv[i] = __float2half_rn(tile[cc][tok] * sc + of);
    }
    __half* dst = g_ht + ((size_t)bb * HWSZ + t0 + tok) * 256 + gg * 32 + seg * 16;
    *(uint4*)dst       = *(uint4*)hv;
    *(uint4*)(dst + 8) = *(uint4*)(hv + 8);
}

// ============================================================
// fp16 tensor-core GEMM, 3-stage cp.async ring pipeline.
// ============================================================
#define LDWH 20
#define TILEW (128 * LDWH)
#define GEMM_SMEM_BYTES (6 * TILEW * 4)
#define QSCALE 0.18033688011112042f
#define EPL 136

template<int M_TOTAL, bool QKV_MODE>
__global__ void __launch_bounds__(256, 2) gemm_h_kernel(
        const __half* __restrict__ A,
        const __half* __restrict__ Bt,
        const float* __restrict__ bias,
        const float* __restrict__ resid,
        float* __restrict__ out) {
    extern __shared__ uint32_t sw[];
    uint32_t* a_s = sw;                   // 3 stages [128][20w]
    uint32_t* b_s = sw + 3 * TILEW;       // 3 stages [128][20w]
    const uint32_t a_u = smem_u32(a_s);
    const uint32_t b_u = smem_u32(b_s);

    const int tid = threadIdx.x, lane = tid & 31, wid = tid >> 5;
    const int g4 = lane >> 2, t4 = lane & 3;
    const int wm = wid >> 1, wn = wid & 1;
    const int bb = blockIdx.z;
    const int m0 = blockIdx.y * 128;
    const int n0 = blockIdx.x * 128;
    const __half* Bp = Bt + (size_t)bb * HWSZ * 256 + (size_t)n0 * 256;

    float acc[2][8][4];
    #pragma unroll
    for (int mt = 0; mt < 2; mt++)
        #pragma unroll
        for (int nt = 0; nt < 8; nt++)
            #pragma unroll
            for (int i = 0; i < 4; i++) acc[mt][nt][i] = 0.f;

    // prologue: stages 0 and 1
    #pragma unroll
    for (int t = 0; t < 2; t++) {
        const int k0 = t * 32;
        #pragma unroll 2
        for (int e = tid; e < 512; e += 256) {
            int r = e >> 2, c8 = e & 3;
            cp16(a_u + (t * TILEW + r * LDWH + c8 * 4) * 4,
                 A + (size_t)(m0 + r) * 256 + k0 + c8 * 8);
        }
        #pragma unroll 2
        for (int e = tid; e < 512; e += 256) {
            int r = e >> 2, c8 = e & 3;
            cp16(b_u + (t * TILEW + r * LDWH + c8 * 4) * 4,
                 Bp + (size_t)r * 256 + k0 + c8 * 8);
        }
        CP_COMMIT();
    }

    int buf = 0;
    for (int j = 0; j < 8; j++) {
        const uint32_t* at = a_s + buf * TILEW;
        const uint32_t* bt = b_s + buf * TILEW;

        if (j < 7) CP_WAIT1(); else CP_WAIT0();
        __syncthreads();

        if (j < 6) {
            int nb = buf + 2; if (nb >= 3) nb -= 3;
            const int k0 = (j + 2) * 32;
            #pragma unroll 2
            for (int e = tid; e < 512; e += 256) {
                int r = e >> 2, c8 = e & 3;
                cp16(a_u + (nb * TILEW + r * LDWH + c8 * 4) * 4,
                     A + (size_t)(m0 + r) * 256 + k0 + c8 * 8);
            }
            #pragma unroll 2
            for (int e = tid; e < 512; e += 256) {
                int r = e >> 2, c8 = e & 3;
                cp16(b_u + (nb * TILEW + r * LDWH + c8 * 4) * 4,
                     Bp + (size_t)r * 256 + k0 + c8 * 8);
            }
            CP_COMMIT();
        }

        #pragma unroll
        for (int kt = 0; kt < 2; kt++) {
            uint32_t af[2][4];
            #pragma unroll
            for (int mt = 0; mt < 2; mt++) {
                const uint32_t* ap = at + (wm * 32 + mt * 16 + g4) * LDWH + kt * 8 + t4;
                af[mt][0] = ap[0];
                af[mt][1] = ap[8 * LDWH];
                af[mt][2] = ap[4];
                af[mt][3] = ap[8 * LDWH + 4];
            }
            const uint32_t* bp = bt + (wn * 64 + g4) * LDWH + kt * 8 + t4;
            #pragma unroll
            for (int nt = 0; nt < 8; nt++) {
                uint32_t b0 = bp[nt * 8 * LDWH];
                uint32_t b1 = bp[nt * 8 * LDWH + 4];
                mma16(acc[0][nt], af[0], b0, b1);
                mma16(acc[1][nt], af[1], b0, b1);
            }
        }

        buf++; if (buf == 3) buf = 0;
    }
    __syncthreads();   // mainloop smem reads done before epilogue staging reuses sw

    // ---- epilogue ----
    if (QKV_MODE) {
        uint16_t* ep = (uint16_t*)sw;
        const bool is_v = (m0 >= 512);
        const float sc = (m0 < 256) ? QSCALE : 1.0f;

        #pragma unroll
        for (int mt = 0; mt < 2; mt++) {
            const int r = wm * 32 + mt * 16 + g4;
            const float bv0 = bias[m0 + r], bv1 = bias[m0 + r + 8];
            #pragma unroll
            for (int nt = 0; nt < 8; nt++) {
                const int tl = wn * 64 + nt * 8 + 2 * t4;
                __half h0 = __float2half_rn((acc[mt][nt][0] + bv0) * sc);
                __half h1 = __float2half_rn((acc[mt][nt][1] + bv0) * sc);
                __half h2 = __float2half_rn((acc[mt][nt][2] + bv1) * sc);
                __half h3 = __float2half_rn((acc[mt][nt][3] + bv1) * sc);
                if (is_v) {
                    __half2 p01; p01.x = h0; p01.y = h1;
                    __half2 p23; p23.x = h2; p23.y = h3;
                    *(__half2*)&ep[(r)     * EPL + tl] = p01;
                    *(__half2*)&ep[(r + 8) * EPL + tl] = p23;
                } else {
                    ep[(tl)     * EPL + r]     = __half_as_ushort(h0);
                    ep[(tl + 1) * EPL + r]     = __half_as_ushort(h1);
                    ep[(tl)     * EPL + r + 8] = __half_as_ushort(h2);
                    ep[(tl + 1) * EPL + r + 8] = __half_as_ushort(h3);
                }
            }
        }
        __syncthreads();

        #pragma unroll
        for (int e = tid; e < 2048; e += 256) {
            const int a = e >> 4, c8 = e & 15;
            uint4 val = *(uint4*)&ep[a * EPL + c8 * 8];
            if (is_v) {
                const int ch = m0 - 512 + a;
                __half* gv = g_vh + ((size_t)(bb * 4 + (ch >> 6)) * 64 + (ch & 63)) * HWSZ
                           + n0 + c8 * 8;
                *(uint4*)gv = val;
            } else {
                const int gm = m0 + c8 * 8;
                const int tok = n0 + a;
                if (gm < 256) {
                    __half* gq = g_qh + ((size_t)(bb * 4 + (gm >> 6)) * HWSZ + tok) * 64
                               + (gm & 63);
                    *(uint4*)gq = val;
                } else {
                    __half* gk = g_kh + ((size_t)(bb * 4 + ((gm - 256) >> 6)) * HWSZ + tok) * 64
                               + (gm & 63);
                    *(uint4*)gk = val;
                }
            }
        }
    } else {
        #pragma unroll
        for (int mt = 0; mt < 2; mt++) {
            const int r0 = m0 + wm * 32 + mt * 16 + g4;
            const float bv0 = bias[r0], bv1 = bias[r0 + 8];
            #pragma unroll
            for (int nt = 0; nt < 8; nt++) {
                const int tok = n0 + wn * 64 + nt * 8 + 2 * t4;
                float v0 = acc[mt][nt][0] + bv0;
                float v1 = acc[mt][nt][1] + bv0;
                float v2 = acc[mt][nt][2] + bv1;
                float v3 = acc[mt][nt][3] + bv1;
                const float* rp = resid + ((size_t)bb * 256 + r0) * HWSZ + tok;
                float* op = out + ((size_t)bb * 256 + r0) * HWSZ + tok;
                float2 ra = *(const float2*)rp;
                float2 rb = *(const float2*)(rp + 8 * HWSZ);
                *(float2*)op              = make_float2(v0 + ra.x, v1 + ra.y);
                *(float2*)(op + 8 * HWSZ) = make_float2(v2 + rb.x, v3 + rb.y);
            }
        }
    }
}

// ============================================================
// fp16 flash attention: BM=256, 2-stage (exact R12/R15 best config).
// ============================================================
#define LDW 36
#define KVW (64 * LDW)
#define ATTN_SMEM_BYTES (4 * KVW * 4)
#define ONE2 0x3C003C00u

__global__ void __launch_bounds__(256) attn_mma_kernel() {
    extern __shared__ uint32_t smw[];
    uint32_t* ks_base = smw;
    uint32_t* vs_base = smw + 2 * KVW;

    const int tid = threadIdx.x, lane = tid & 31, wid = tid >> 5;
    const int g4 = lane >> 2, t4 = lane & 3;
    const int bh = blockIdx.y;
    const int bb = bh >> 2, hh = bh & 3;
    const int i0 = blockIdx.x * 256;
    const int wrow = wid * 32;

    const __half* qg = g_qh + (size_t)bh * HWSZ * 64;
    const __half* kg = g_kh + (size_t)bh * HWSZ * 64;
    const __half* vg = g_vh + (size_t)bh * 64 * HWSZ;

    const uint32_t ks_u = smem_u32(ks_base);
    const uint32_t vs_u = smem_u32(vs_base);

    const int lm_m = lane >> 3;
    const uint32_t lm_row = (uint32_t)(((lm_m >> 1) * 8) + (lane & 7));
    const uint32_t lm_kb  = (uint32_t)((lm_m & 1) * 16);

    uint32_t qf[2][4][4];
    #pragma unroll
    for (int mt = 0; mt < 2; mt++) {
        const __half* qr0 = qg + (size_t)(i0 + wrow + mt * 16 + g4) * 64;
        const __half* qr1 = qr0 + 8 * 64;
        #pragma unroll
        for (int kt = 0; kt < 4; kt++) {
            qf[mt][kt][0] = *(const uint32_t*)(qr0 + kt * 16 + 2 * t4);
            qf[mt][kt][1] = *(const uint32_t*)(qr1 + kt * 16 + 2 * t4);
            qf[mt][kt][2] = *(const uint32_t*)(qr0 + kt * 16 + 2 * t4 + 8);
            qf[mt][kt][3] = *(const uint32_t*)(qr1 + kt * 16 + 2 * t4 + 8);
        }
    }

    float of[2][9][4];
    #pragma unroll
    for (int mt = 0; mt < 2; mt++)
        #pragma unroll
        for (int nt = 0; nt < 9; nt++)
            #pragma unroll
            for (int i = 0; i < 4; i++) of[mt][nt][i] = 0.f;

    #pragma unroll 2
    for (int e = tid; e < 512; e += 256) {
        int r = e >> 3, c = e & 7;
        cp16(ks_u + (r * LDW) * 4 + c * 16, kg + (size_t)r * 64 + c * 8);
    }
    #pragma unroll 2
    for (int e = tid; e < 512; e += 256) {
        int r = e >> 3, c = e & 7;
        cp16(vs_u + (r * LDW) * 4 + c * 16, vg + (size_t)r * HWSZ + c * 8);
    }
    CP_COMMIT();

    for (int j = 0; j < 64; j++) {
        const int buf = j & 1;
        const uint32_t klm = ks_u + (buf * KVW + lm_row * LDW) * 4 + lm_kb;
        const uint32_t vlm = vs_u + (buf * KVW + lm_row * LDW) * 4 + lm_kb;

        CP_WAIT0();
        __syncthreads();

        if (j < 63) {
            const uint32_t kd = ks_u + ((buf ^ 1) * KVW) * 4;
            const uint32_t vd = vs_u + ((buf ^ 1) * KVW) * 4;
            const __half* kn = kg + (size_t)(j + 1) * 64 * 64;
            const __half* vn = vg + (j + 1) * 64;
            #pragma unroll 2
            for (int e = tid; e < 512; e += 256) {
                int r = e >> 3, c = e & 7;
                cp16(kd + (r * LDW) * 4 + c * 16, kn + (size_t)r * 64 + c * 8);
            }
            #pragma unroll 2
            for (int e = tid; e < 512; e += 256) {
                int r = e >> 3, c = e & 7;
                cp16(vd + (r * LDW) * 4 + c * 16, vn + (size_t)r * HWSZ + c * 8);
            }
            CP_COMMIT();
        }

        float sf[2][8][4];
        #pragma unroll
        for (int mt = 0; mt < 2; mt++)
            #pragma unroll
            for (int nt = 0; nt < 8; nt++)
                #pragma unroll
                for (int i = 0; i < 4; i++) sf[mt][nt][i] = 0.f;

        // ---- S_A ----
        #pragma unroll
        for (int kt = 0; kt < 4; kt++) {
            #pragma unroll
            for (int ntp = 0; ntp < 2; ntp++) {
                uint32_t br[4];
                ldsm4(br, klm + (ntp * 16 * LDW) * 4 + kt * 32);
                mma16(sf[0][2 * ntp],     qf[0][kt], br[0], br[1]);
                mma16(sf[1][2 * ntp],     qf[1][kt], br[0], br[1]);
                mma16(sf[0][2 * ntp + 1], qf[0][kt], br[2], br[3]);
                mma16(sf[1][2 * ntp + 1], qf[1][kt], br[2], br[3]);
            }
        }

        uint32_t pa[2][4][4];

        // ---- S_B || ex2_A ----
        #pragma unroll
        for (int kt = 0; kt < 4; kt++) {
            #pragma unroll
            for (int ntp = 2; ntp < 4; ntp++) {
                uint32_t br[4];
                ldsm4(br, klm + (ntp * 16 * LDW) * 4 + kt * 32);
                mma16(sf[0][2 * ntp],     qf[0][kt], br[0], br[1]);
                mma16(sf[1][2 * ntp],     qf[1][kt], br[0], br[1]);
                mma16(sf[0][2 * ntp + 1], qf[0][kt], br[2], br[3]);
                mma16(sf[1][2 * ntp + 1], qf[1][kt], br[2], br[3]);
            }
        }
        #pragma unroll
        for (int mt = 0; mt < 2; mt++)
            #pragma unroll
            for (int nt = 0; nt < 4; nt++) {
                float p0 = ex2f(sf[mt][nt][0]);
                float p1 = ex2f(sf[mt][nt][1]);
                float p2 = ex2f(sf[mt][nt][2]);
                float p3 = ex2f(sf[mt][nt][3]);
                pa[mt][nt >> 1][(nt & 1) * 2]     = pack_h2(p0, p1);
                pa[mt][nt >> 1][(nt & 1) * 2 + 1] = pack_h2(p2, p3);
            }

        // ---- PV_A || ex2_B ----
        #pragma unroll
        for (int kt = 0; kt < 2; kt++) {
            #pragma unroll
            for (int ntp = 0; ntp < 4; ntp++) {
                uint32_t br[4];
                ldsm4(br, vlm + (ntp * 16 * LDW) * 4 + kt * 32);
                mma16(of[0][2 * ntp],     pa[0][kt], br[0], br[1]);
                mma16(of[1][2 * ntp],     pa[1][kt], br[0], br[1]);
                mma16(of[0][2 * ntp + 1], pa[0][kt], br[2], br[3]);
                mma16(of[1][2 * ntp + 1], pa[1][kt], br[2], br[3]);
            }
            mma16(of[0][8], pa[0][kt], ONE2, ONE2);
            mma16(of[1][8], pa[1][kt], ONE2, ONE2);
        }
        #pragma unroll
        for (int mt = 0; mt < 2; mt++)
            #pragma unroll
            for (int nt = 4; nt < 8; nt++) {
                float p0 = ex2f(sf[mt][nt][0]);
                float p1 = ex2f(sf[mt][nt][1]);
                float p2 = ex2f(sf[mt][nt][2]);
                float p3 = ex2f(sf[mt][nt][3]);
                pa[mt][nt >> 1][(nt & 1) * 2]     = pack_h2(p0, p1);
                pa[mt][nt >> 1][(nt & 1) * 2 + 1] = pack_h2(p2, p3);
            }

        // ---- PV_B ----
        #pragma unroll
        for (int kt = 2; kt < 4; kt++) {
            #pragma unroll
            for (int ntp = 0; ntp < 4; ntp++) {
                uint32_t br[4];
                ldsm4(br, vlm + (ntp * 16 * LDW) * 4 + kt * 32);
                mma16(of[0][2 * ntp],     pa[0][kt], br[0], br[1]);
                mma16(of[1][2 * ntp],     pa[1][kt], br[0], br[1]);
                mma16(of[0][2 * ntp + 1], pa[0][kt], br[2], br[3]);
                mma16(of[1][2 * ntp + 1], pa[1][kt], br[2], br[3]);
            }
            mma16(of[0][8], pa[0][kt], ONE2, ONE2);
            mma16(of[1][8], pa[1][kt], ONE2, ONE2);
        }
    }

    #pragma unroll
    for (int mt = 0; mt < 2; mt++) {
        float inv0 = 1.f / of[mt][8][0];
        float inv1 = 1.f / of[mt][8][2];
        int tok = i0 + wrow + mt * 16 + g4;
        __half* d0 = g_oh + ((size_t)bb * HWSZ + tok) * 256 + hh * 64;
        __half* d1 = d0 + 8 * 256;
        #pragma unroll
        for (int nt = 0; nt < 8; nt++) {
            int ch = nt * 8 + 2 * t4;
            *(__half2*)(d0 + ch) = __floats2half2_rn(of[mt][nt][0] * inv0,
                                                     of[mt][nt][1] * inv0);
            *(__half2*)(d1 + ch) = __floats2half2_rn(of[mt][nt][2] * inv1,
                                                     of[mt][nt][3] * inv1);
        }
    }
}

// ============================================================
extern "C" void kernel_launch(void* const* d_in, const int* in_sizes, int n_in,
                              void* d_out, int out_size) {
    const float* x      = (const float*)d_in[0];
    const float* norm_w = (const float*)d_in[1];
    const float* norm_b = (const float*)d_in[2];
    const float* qkv_w  = (const float*)d_in[3];
    const float* qkv_b  = (const float*)d_in[4];
    const float* proj_w = (const float*)d_in[5];
    const float* proj_b = (const float*)d_in[6];
    float* out = (float*)d_out;

    void *pht, *poh, *pwq, *pwp;
    cudaGetSymbolAddress(&pht, g_ht);
    cudaGetSymbolAddress(&poh, g_oh);
    cudaGetSymbolAddress(&pwq, g_wqkv);
    cudaGetSymbolAddress(&pwp, g_wproj);

    cudaFuncSetAttribute(gemm_h_kernel<768, true>,
                         cudaFuncAttributeMaxDynamicSharedMemorySize, GEMM_SMEM_BYTES);
    cudaFuncSetAttribute(gemm_h_kernel<256, false>,
                         cudaFuncAttributeMaxDynamicSharedMemorySize, GEMM_SMEM_BYTES);
    cudaFuncSetAttribute(attn_mma_kernel,
                         cudaFuncAttributeMaxDynamicSharedMemorySize, ATTN_SMEM_BYTES);

    gn_partial_conv_kernel<<<832, 256>>>(x, qkv_w, proj_w);
    gn_norm_kernel<<<dim3(HWSZ / 128, 32), 256>>>(x, norm_w, norm_b);

    gemm_h_kernel<768, true><<<dim3(HWSZ / 128, 768 / 128, BATCH), 256, GEMM_SMEM_BYTES>>>(
        (const __half*)pwq, (const __half*)pht, qkv_b, nullptr, nullptr);

    attn_mma_kernel<<<dim3(HWSZ / 256, NBH), 256, ATTN_SMEM_BYTES>>>();

    gemm_h_kernel<256, false><<<dim3(HWSZ / 128, 256 / 128, BATCH), 256, GEMM_SMEM_BYTES>>>(
        (const __half*)pwp, (const __half*)poh, proj_b, x, out);
}